// round 5
// baseline (speedup 1.0000x reference)
#include <cuda_runtime.h>
#include <math.h>
#include <stdint.h>

#define NRTOK 16384
#define NTOK  32768      // B*Nr
#define MM    64
#define AD    128
#define HIDN  512
#define TT    64         // tokens per CTA tile
#define HC    32         // hidden chunk
#define SCALE 0.17677669529663687f  // 1/sqrt(32)

#define YT_STR 68        // YsT row stride (floats)
#define W1_STR 36        // W1 chunk row stride (floats)
#define W2_STR 132       // W2 chunk row stride (floats)
#define HD_STR 66        // HsTd row stride (float2 units)

// smem map (bytes):
//   [0, 34816)          YsT  : float[128*68]        y^T tile (persists through MLP)
//   [34816, 53248)      W    : float[4608]           W1 chunk [128][32] s36  OR  W2 chunk [32][128] s132
//   [53248, 70144)      union: HsTd float2[32*66]    dup'd gelu(h)^T   |  attention scratch
#define SM_W_OFF   34816
#define SM_U_OFF   53248
#define SMEM_BYTES 70144

typedef unsigned long long u64;

__device__ __forceinline__ void ffma2(u64& d, u64 a, u64 b) {
    asm("fma.rn.f32x2 %0, %1, %2, %0;" : "+l"(d) : "l"(a), "l"(b));
}
__device__ __forceinline__ u64 pack2(float x) {
    u64 r; asm("mov.b64 %0, {%1, %1};" : "=l"(r) : "f"(x)); return r;
}
__device__ __forceinline__ float2 unpack2(u64 v) {
    float2 r; asm("mov.b64 {%0, %1}, %2;" : "=f"(r.x), "=f"(r.y) : "l"(v)); return r;
}

// scratch: x = post-LN1 (residual base for final add)
__device__ float g_x[NTOK * AD];

__global__ __launch_bounds__(256, 3)
void bev_fused_kernel(const float* __restrict__ Q, const float* __restrict__ K,
                      const float* __restrict__ V, const int* __restrict__ mask,
                      const float* __restrict__ ln1g, const float* __restrict__ ln1b,
                      const float* __restrict__ ln2g, const float* __restrict__ ln2b,
                      const float* __restrict__ W1, const float* __restrict__ b1,
                      const float* __restrict__ W2, const float* __restrict__ b2,
                      float* __restrict__ Out)
{
    extern __shared__ char smem_raw[];
    float*  YsT  = reinterpret_cast<float*>(smem_raw);
    float*  Wsh  = reinterpret_cast<float*>(smem_raw + SM_W_OFF);
    // attention scratch views (union area)
    float*  Ls   = reinterpret_cast<float*>(smem_raw + SM_U_OFF);          // 256
    float*  As   = Ls + 256;                                               // 256
    float*  Ps   = As + 256;                                               // 256
    float*  Ms   = Ps + 256;                                               // 64
    float2* Rs   = reinterpret_cast<float2*>(Ms + MM);                     // 4
    float2* Rs2  = Rs + 4;                                                 // 4
    float2* HsTd = reinterpret_cast<float2*>(smem_raw + SM_U_OFF);         // [32*66]

    const int tid  = threadIdx.x;
    const int lane = tid & 31;
    const int wid  = tid >> 5;
    const size_t T0 = (size_t)blockIdx.x * TT;

    // attention roles: warp w -> head h=w&3, m-base mb=(w>>2)*32, lane = d
    const int hh = wid & 3;
    const int mb = (wid >> 2) << 5;
    const int a  = (hh << 5) + lane;

    // per-thread LN params (a == tid for tid<128)
    float l1gv = 0.f, l1bv = 0.f, l2gv = 0.f, l2bv = 0.f;
    if (tid < AD) {
        l1gv = ln1g[tid]; l1bv = ln1b[tid];
        l2gv = ln2g[tid]; l2bv = ln2b[tid];
    }

    // =========================== phase 1: attention + LN1 + LN2 ===========================
    for (int tl = 0; tl < TT; tl++) {
        const size_t t = T0 + tl;

        if (tid < MM)
            Ms[tid] = mask[((t & (NRTOK - 1)) << 6) + tid] ? -1e30f : 0.0f;

        const float q = Q[t * AD + a];

        // logits: p[i] = q_d * K[mb+i][a], coalesced 128B warp loads
        const float* Kp = K + (t * MM + mb) * AD + a;
        float p[32];
#pragma unroll
        for (int i = 0; i < 32; i++) p[i] = q * Kp[(size_t)i * AD];

        // butterfly transpose-reduce: lane l ends with full d-sum for m = mb + l
#pragma unroll
        for (int s = 16; s >= 1; s >>= 1) {
            const bool hi = (lane & s) != 0;
#pragma unroll
            for (int i = 0; i < 16; i++) {
                if (i < s) {
                    float send = hi ? p[i] : p[i + s];
                    float recv = __shfl_xor_sync(0xffffffffu, send, s);
                    p[i] = (hi ? p[i + s] : p[i]) + recv;
                }
            }
        }
        __syncthreads();                                   // S1: Ms ready, Ls free
        Ls[(hh << 6) + mb + lane] = p[0] * SCALE + Ms[mb + lane];
        __syncthreads();                                   // S2

        // softmax: warp w<4 handles head w over 64 m
        if (wid < 4) {
            float l0 = Ls[(wid << 6) + lane];
            float l1 = Ls[(wid << 6) + 32 + lane];
            float mx = fmaxf(l0, l1);
#pragma unroll
            for (int s = 16; s >= 1; s >>= 1)
                mx = fmaxf(mx, __shfl_xor_sync(0xffffffffu, mx, s));
            float e0 = __expf(l0 - mx), e1 = __expf(l1 - mx);
            float ss = e0 + e1;
#pragma unroll
            for (int s = 16; s >= 1; s >>= 1)
                ss += __shfl_xor_sync(0xffffffffu, ss, s);
            float inv = 1.0f / ss;
            As[(wid << 6) + lane]      = e0 * inv;
            As[(wid << 6) + 32 + lane] = e1 * inv;
        }
        __syncthreads();                                   // S3

        // out[a] = sum_m attn[h][m] * V[m][a], coalesced V stream
        {
            const int aV = tid & 127;
            const int gV = tid >> 7;
            const int hA = aV >> 5;
            const float* Vp = V + (t * MM + ((size_t)gV << 5)) * AD + aV;
            float acc = 0.0f;
#pragma unroll
            for (int i = 0; i < 32; i++)
                acc += As[(hA << 6) + (gV << 5) + i] * Vp[(size_t)i * AD];
            Ps[tid] = acc;
        }
        __syncthreads();                                   // S4

        float x = 0.0f, xn = 0.0f;
        if (tid < AD) {
            x = q + Ps[tid] + Ps[tid + 128];
            float sx = x, sxx = x * x;
#pragma unroll
            for (int s = 16; s >= 1; s >>= 1) {
                sx  += __shfl_xor_sync(0xffffffffu, sx,  s);
                sxx += __shfl_xor_sync(0xffffffffu, sxx, s);
            }
            if (lane == 0) Rs[wid] = make_float2(sx, sxx);
        }
        __syncthreads();                                   // S5
        if (tid < AD) {
            float tsum = Rs[0].x + Rs[1].x + Rs[2].x + Rs[3].x;
            float tsq  = Rs[0].y + Rs[1].y + Rs[2].y + Rs[3].y;
            float mu   = tsum * (1.0f / AD);
            float var  = tsq * (1.0f / AD) - mu * mu;
            float rstd = rsqrtf(var + 1e-5f);
            xn = (x - mu) * rstd * l1gv + l1bv;
            float sx = xn, sxx = xn * xn;
#pragma unroll
            for (int s = 16; s >= 1; s >>= 1) {
                sx  += __shfl_xor_sync(0xffffffffu, sx,  s);
                sxx += __shfl_xor_sync(0xffffffffu, sxx, s);
            }
            if (lane == 0) Rs2[wid] = make_float2(sx, sxx);
        }
        __syncthreads();                                   // S6
        if (tid < AD) {
            float tsum = Rs2[0].x + Rs2[1].x + Rs2[2].x + Rs2[3].x;
            float tsq  = Rs2[0].y + Rs2[1].y + Rs2[2].y + Rs2[3].y;
            float mu2   = tsum * (1.0f / AD);
            float var2  = tsq * (1.0f / AD) - mu2 * mu2;
            float rstd2 = rsqrtf(var2 + 1e-5f);
            float y = (xn - mu2) * rstd2 * l2gv + l2bv;
            g_x[t * AD + tid] = xn;
            YsT[tid * YT_STR + tl] = y;
        }
    }

    // =========================== phase 2: MLP on the tile ===========================
    // GEMM1 tile: 4 tokens x 2 hid (token-pair packed). GEMM2 tile: 4 tokens x 8 out cols.
    const int tg = tid >> 4;         // 16 token-groups
    const int cg = tid & 15;         // 16 col-groups
    const int t0 = tg << 2;          // tokens t0..t0+3
    const int j0 = cg << 1;          // GEMM1 hid cols j0, j0+1
    const int c0 = cg << 2;          // GEMM2 out cols c0..c0+3 and c0+64..c0+67

    u64 acc2p[16];                   // [t][4]: {lowPair0, lowPair1, hiPair0, hiPair1}
#pragma unroll
    for (int i = 0; i < 16; i++) acc2p[i] = 0ULL;

    for (int c = 0; c < HIDN / HC; c++) {
        __syncthreads();   // HsTd free (prev GEMM2 done), W free; also attn->MLP transition

        // ---- stage W1 chunk [128 k][32 j] (float4, coalesced) ----
        const float* W1c = W1 + c * HC;
#pragma unroll
        for (int i = 0; i < 4; i++) {
            int e  = tid + 256 * i;              // 1024 float4
            int k  = e >> 3;
            int j4 = (e & 7) << 2;
            float4 v = *reinterpret_cast<const float4*>(&W1c[(size_t)k * HIDN + j4]);
            *reinterpret_cast<float4*>(&Wsh[k * W1_STR + j4]) = v;
        }
        __syncthreads();

        // ---- GEMM1: acc1p[2 tokpair][2 hid] (f32x2 over token pairs) ----
        u64 acc1p[4] = {0ULL, 0ULL, 0ULL, 0ULL};    // [jj*2 + tp]
#pragma unroll 4
        for (int k = 0; k < AD; k++) {
            ulonglong2 y2 = *reinterpret_cast<const ulonglong2*>(&YsT[k * YT_STR + t0]);
            float2 w2 = *reinterpret_cast<const float2*>(&Wsh[k * W1_STR + j0]);
            u64 w0 = pack2(w2.x), w1 = pack2(w2.y);
            ffma2(acc1p[0], y2.x, w0);
            ffma2(acc1p[1], y2.y, w0);
            ffma2(acc1p[2], y2.x, w1);
            ffma2(acc1p[3], y2.y, w1);
        }

        // ---- bias + exact gelu -> HsTd (duplicated pairs) ----
#pragma unroll
        for (int jj = 0; jj < 2; jj++) {
            float bj = __ldg(&b1[c * HC + j0 + jj]);
#pragma unroll
            for (int tp = 0; tp < 2; tp++) {
                float2 h = unpack2(acc1p[jj * 2 + tp]);
                h.x += bj; h.y += bj;
                float gx = 0.5f * h.x * (1.0f + erff(h.x * 0.70710678118654752f));
                float gy = 0.5f * h.y * (1.0f + erff(h.y * 0.70710678118654752f));
                HsTd[(j0 + jj) * HD_STR + t0 + tp * 2 + 0] = make_float2(gx, gx);
                HsTd[(j0 + jj) * HD_STR + t0 + tp * 2 + 1] = make_float2(gy, gy);
            }
        }
        __syncthreads();   // W free (GEMM1 done), HsTd ready

        // ---- stage W2 chunk [32 j][128 a] (float4, coalesced) ----
        const float* W2c = W2 + (size_t)(c * HC) * AD;
#pragma unroll
        for (int i = 0; i < 4; i++) {
            int e  = tid + 256 * i;              // 1024 float4
            int j  = e >> 5;
            int a4 = (e & 31) << 2;
            float4 v = *reinterpret_cast<const float4*>(&W2c[(size_t)j * AD + a4]);
            *reinterpret_cast<float4*>(&Wsh[j * W2_STR + a4]) = v;
        }
        __syncthreads();

        // ---- GEMM2: acc2p += Hchunk @ W2chunk (all operands pre-packed f32x2) ----
#pragma unroll 4
        for (int j = 0; j < HC; j++) {
            ulonglong2 gA = *reinterpret_cast<const ulonglong2*>(&HsTd[j * HD_STR + t0]);     // (g0,g0),(g1,g1)
            ulonglong2 gB = *reinterpret_cast<const ulonglong2*>(&HsTd[j * HD_STR + t0 + 2]); // (g2,g2),(g3,g3)
            ulonglong2 wA = *reinterpret_cast<const ulonglong2*>(&Wsh[j * W2_STR + c0]);
            ulonglong2 wB = *reinterpret_cast<const ulonglong2*>(&Wsh[j * W2_STR + c0 + 64]);
            ffma2(acc2p[0],  gA.x, wA.x); ffma2(acc2p[1],  gA.x, wA.y);
            ffma2(acc2p[2],  gA.x, wB.x); ffma2(acc2p[3],  gA.x, wB.y);
            ffma2(acc2p[4],  gA.y, wA.x); ffma2(acc2p[5],  gA.y, wA.y);
            ffma2(acc2p[6],  gA.y, wB.x); ffma2(acc2p[7],  gA.y, wB.y);
            ffma2(acc2p[8],  gB.x, wA.x); ffma2(acc2p[9],  gB.x, wA.y);
            ffma2(acc2p[10], gB.x, wB.x); ffma2(acc2p[11], gB.x, wB.y);
            ffma2(acc2p[12], gB.y, wA.x); ffma2(acc2p[13], gB.y, wA.y);
            ffma2(acc2p[14], gB.y, wB.x); ffma2(acc2p[15], gB.y, wB.y);
        }
    }

    // ---- epilogue: out = x + acc2 + b2 (float4) ----
#pragma unroll
    for (int tt2 = 0; tt2 < 4; tt2++) {
        size_t row = (T0 + t0 + tt2) * (size_t)AD;
        float2 lo0 = unpack2(acc2p[tt2 * 4 + 0]);
        float2 lo1 = unpack2(acc2p[tt2 * 4 + 1]);
        float2 hi0 = unpack2(acc2p[tt2 * 4 + 2]);
        float2 hi1 = unpack2(acc2p[tt2 * 4 + 3]);
        {
            float4 xv = *reinterpret_cast<const float4*>(&g_x[row + c0]);
            float4 o;
            o.x = xv.x + lo0.x + __ldg(&b2[c0 + 0]);
            o.y = xv.y + lo0.y + __ldg(&b2[c0 + 1]);
            o.z = xv.z + lo1.x + __ldg(&b2[c0 + 2]);
            o.w = xv.w + lo1.y + __ldg(&b2[c0 + 3]);
            *reinterpret_cast<float4*>(&Out[row + c0]) = o;
        }
        {
            float4 xv = *reinterpret_cast<const float4*>(&g_x[row + c0 + 64]);
            float4 o;
            o.x = xv.x + hi0.x + __ldg(&b2[c0 + 64]);
            o.y = xv.y + hi0.y + __ldg(&b2[c0 + 65]);
            o.z = xv.z + hi1.x + __ldg(&b2[c0 + 66]);
            o.w = xv.w + hi1.y + __ldg(&b2[c0 + 67]);
            *reinterpret_cast<float4*>(&Out[row + c0 + 64]) = o;
        }
    }
}

// ===========================================================================
extern "C" void kernel_launch(void* const* d_in, const int* in_sizes, int n_in,
                              void* d_out, int out_size)
{
    const float* Q    = (const float*)d_in[0];
    const float* K    = (const float*)d_in[1];
    const float* V    = (const float*)d_in[2];
    const int*   mask = (const int*)  d_in[3];
    const float* ln1g = (const float*)d_in[4];
    const float* ln1b = (const float*)d_in[5];
    const float* ln2g = (const float*)d_in[6];
    const float* ln2b = (const float*)d_in[7];
    const float* W1   = (const float*)d_in[8];
    const float* b1   = (const float*)d_in[9];
    const float* W2   = (const float*)d_in[10];
    const float* b2   = (const float*)d_in[11];
    float* Out = (float*)d_out;

    static bool attr_set = false;
    if (!attr_set) {
        cudaFuncSetAttribute(bev_fused_kernel,
                             cudaFuncAttributeMaxDynamicSharedMemorySize,
                             SMEM_BYTES);
        attr_set = true;
    }

    bev_fused_kernel<<<NTOK / TT, 256, SMEM_BYTES>>>(
        Q, K, V, mask, ln1g, ln1b, ln2g, ln2b, W1, b1, W2, b2, Out);
}

// round 6
// speedup vs baseline: 1.4466x; 1.4466x over previous
#include <cuda_runtime.h>
#include <math.h>
#include <stdint.h>

#define NRTOK 16384
#define NTOK  32768      // B*Nr
#define MM    64
#define AD    128
#define HIDN  512
#define TT    64         // tokens per CTA tile
#define HC    64         // hidden chunk
#define SCALE 0.17677669529663687f  // 1/sqrt(32)

#define YT_STR 68        // YsT row stride (floats)
#define W1_STR 68        // W1 chunk row stride (floats)
#define W2_STR 132       // W2 chunk row stride (floats)
#define HD_STR 66        // HsTd row stride (float2 units, even => 16B-aligned rows)

// smem map (bytes):
//   [0, 34816)        YsT : float[128*68]   y^T tile (persists through MLP)
//   [34816, 69632)    W   : float[8704]     W1 chunk [128][64] s68  OR  W2 chunk [64][128] s132
//   [69632, 103424)   union: HsTd float2[64*66] dup'd gelu(h)^T | attention scratch
#define SM_W_OFF   34816
#define SM_U_OFF   69632
#define SMEM_BYTES 103424

typedef unsigned long long u64;

__device__ __forceinline__ void ffma2(u64& d, u64 a, u64 b) {
    asm("fma.rn.f32x2 %0, %1, %2, %0;" : "+l"(d) : "l"(a), "l"(b));
}
__device__ __forceinline__ u64 pack2(float x) {
    u64 r; asm("mov.b64 %0, {%1, %1};" : "=l"(r) : "f"(x)); return r;
}
__device__ __forceinline__ float2 unpack2(u64 v) {
    float2 r; asm("mov.b64 {%0, %1}, %2;" : "=f"(r.x), "=f"(r.y) : "l"(v)); return r;
}

// scratch: x = post-LN1 (residual base for final add)
__device__ float g_x[NTOK * AD];

__global__ __launch_bounds__(256, 2)
void bev_fused_kernel(const float* __restrict__ Q, const float* __restrict__ K,
                      const float* __restrict__ V, const int* __restrict__ mask,
                      const float* __restrict__ ln1g, const float* __restrict__ ln1b,
                      const float* __restrict__ ln2g, const float* __restrict__ ln2b,
                      const float* __restrict__ W1, const float* __restrict__ b1,
                      const float* __restrict__ W2, const float* __restrict__ b2,
                      float* __restrict__ Out)
{
    extern __shared__ char smem_raw[];
    float*  YsT  = reinterpret_cast<float*>(smem_raw);
    float*  Wsh  = reinterpret_cast<float*>(smem_raw + SM_W_OFF);
    // attention scratch views (union area)
    float*  Ls   = reinterpret_cast<float*>(smem_raw + SM_U_OFF);          // 256
    float*  As   = Ls + 256;                                               // 256
    float*  Ps   = As + 256;                                               // 256
    float*  Ms   = Ps + 256;                                               // 64
    float2* Rs   = reinterpret_cast<float2*>(Ms + MM);                     // 4
    float2* Rs2  = Rs + 4;                                                 // 4
    float2* HsTd = reinterpret_cast<float2*>(smem_raw + SM_U_OFF);         // [64*66]

    const int tid  = threadIdx.x;
    const int lane = tid & 31;
    const int wid  = tid >> 5;
    const size_t T0 = (size_t)blockIdx.x * TT;

    // attention roles: warp w -> head h=w&3, m-base mb=(w>>2)*32, lane = d
    const int hh = wid & 3;
    const int mb = (wid >> 2) << 5;
    const int a  = (hh << 5) + lane;

    // per-thread LN params (a == tid for tid<128)
    float l1gv = 0.f, l1bv = 0.f, l2gv = 0.f, l2bv = 0.f;
    if (tid < AD) {
        l1gv = ln1g[tid]; l1bv = ln1b[tid];
        l2gv = ln2g[tid]; l2bv = ln2b[tid];
    }

    // =========================== phase 1: attention + LN1 + LN2 ===========================
    for (int tl = 0; tl < TT; tl++) {
        const size_t t = T0 + tl;

        if (tid < MM)
            Ms[tid] = mask[((t & (NRTOK - 1)) << 6) + tid] ? -1e30f : 0.0f;

        const float q = Q[t * AD + a];

        // logits: p[i] = q_d * K[mb+i][a], coalesced 128B warp loads
        const float* Kp = K + (t * MM + mb) * AD + a;
        float p[32];
#pragma unroll
        for (int i = 0; i < 32; i++) p[i] = q * Kp[(size_t)i * AD];

        // butterfly transpose-reduce: lane l ends with full d-sum for m = mb + l
#pragma unroll
        for (int s = 16; s >= 1; s >>= 1) {
            const bool hi = (lane & s) != 0;
#pragma unroll
            for (int i = 0; i < 16; i++) {
                if (i < s) {
                    float send = hi ? p[i] : p[i + s];
                    float recv = __shfl_xor_sync(0xffffffffu, send, s);
                    p[i] = (hi ? p[i + s] : p[i]) + recv;
                }
            }
        }
        __syncthreads();                                   // S1: Ms ready, Ls free
        Ls[(hh << 6) + mb + lane] = p[0] * SCALE + Ms[mb + lane];
        __syncthreads();                                   // S2

        // softmax: warp w<4 handles head w over 64 m
        if (wid < 4) {
            float l0 = Ls[(wid << 6) + lane];
            float l1 = Ls[(wid << 6) + 32 + lane];
            float mx = fmaxf(l0, l1);
#pragma unroll
            for (int s = 16; s >= 1; s >>= 1)
                mx = fmaxf(mx, __shfl_xor_sync(0xffffffffu, mx, s));
            float e0 = __expf(l0 - mx), e1 = __expf(l1 - mx);
            float ss = e0 + e1;
#pragma unroll
            for (int s = 16; s >= 1; s >>= 1)
                ss += __shfl_xor_sync(0xffffffffu, ss, s);
            float inv = 1.0f / ss;
            As[(wid << 6) + lane]      = e0 * inv;
            As[(wid << 6) + 32 + lane] = e1 * inv;
        }
        __syncthreads();                                   // S3

        // out[a] = sum_m attn[h][m] * V[m][a], coalesced V stream
        {
            const int aV = tid & 127;
            const int gV = tid >> 7;
            const int hA = aV >> 5;
            const float* Vp = V + (t * MM + ((size_t)gV << 5)) * AD + aV;
            float acc = 0.0f;
#pragma unroll
            for (int i = 0; i < 32; i++)
                acc += As[(hA << 6) + (gV << 5) + i] * Vp[(size_t)i * AD];
            Ps[tid] = acc;
        }
        __syncthreads();                                   // S4

        float x = 0.0f, xn = 0.0f;
        if (tid < AD) {
            x = q + Ps[tid] + Ps[tid + 128];
            float sx = x, sxx = x * x;
#pragma unroll
            for (int s = 16; s >= 1; s >>= 1) {
                sx  += __shfl_xor_sync(0xffffffffu, sx,  s);
                sxx += __shfl_xor_sync(0xffffffffu, sxx, s);
            }
            if (lane == 0) Rs[wid] = make_float2(sx, sxx);
        }
        __syncthreads();                                   // S5
        if (tid < AD) {
            float tsum = Rs[0].x + Rs[1].x + Rs[2].x + Rs[3].x;
            float tsq  = Rs[0].y + Rs[1].y + Rs[2].y + Rs[3].y;
            float mu   = tsum * (1.0f / AD);
            float var  = tsq * (1.0f / AD) - mu * mu;
            float rstd = rsqrtf(var + 1e-5f);
            xn = (x - mu) * rstd * l1gv + l1bv;
            float sx = xn, sxx = xn * xn;
#pragma unroll
            for (int s = 16; s >= 1; s >>= 1) {
                sx  += __shfl_xor_sync(0xffffffffu, sx,  s);
                sxx += __shfl_xor_sync(0xffffffffu, sxx, s);
            }
            if (lane == 0) Rs2[wid] = make_float2(sx, sxx);
        }
        __syncthreads();                                   // S6
        if (tid < AD) {
            float tsum = Rs2[0].x + Rs2[1].x + Rs2[2].x + Rs2[3].x;
            float tsq  = Rs2[0].y + Rs2[1].y + Rs2[2].y + Rs2[3].y;
            float mu2   = tsum * (1.0f / AD);
            float var2  = tsq * (1.0f / AD) - mu2 * mu2;
            float rstd2 = rsqrtf(var2 + 1e-5f);
            float y = (xn - mu2) * rstd2 * l2gv + l2bv;
            g_x[t * AD + tid] = xn;
            YsT[tid * YT_STR + tl] = y;
        }
    }

    // =========================== phase 2: MLP on the tile ===========================
    // GEMM1: 4 tokens (2 f32x2 pairs) x 4 hid. GEMM2: 4 tokens x 8 out cols, all f32x2.
    const int tg = tid >> 4;         // 16 token-groups
    const int cg = tid & 15;         // 16 col-groups
    const int t0 = tg << 2;          // tokens t0..t0+3
    const int j0 = cg << 2;          // GEMM1 hid cols j0..j0+3
    const int c0 = cg << 2;          // GEMM2 out cols c0..c0+3 and c0+64..c0+67

    u64 acc2p[16];                   // [t][4]: {loPair0, loPair1, hiPair0, hiPair1}
#pragma unroll
    for (int i = 0; i < 16; i++) acc2p[i] = 0ULL;

    for (int c = 0; c < HIDN / HC; c++) {
        __syncthreads();   // HsTd/W free; also attn->MLP transition on first iter

        // ---- stage W1 chunk [128 k][64 j] (float4, coalesced) ----
        const float* W1c = W1 + c * HC;
#pragma unroll
        for (int i = 0; i < 8; i++) {
            int e  = tid + 256 * i;              // 2048 float4
            int k  = e >> 4;
            int j4 = (e & 15) << 2;
            float4 v = *reinterpret_cast<const float4*>(&W1c[(size_t)k * HIDN + j4]);
            *reinterpret_cast<float4*>(&Wsh[k * W1_STR + j4]) = v;
        }
        __syncthreads();

        // ---- GEMM1: acc1p[jj][tokpair] via f32x2 (token pairs come free from YsT) ----
        u64 acc1p[8];
#pragma unroll
        for (int i = 0; i < 8; i++) acc1p[i] = 0ULL;
#pragma unroll 4
        for (int k = 0; k < AD; k++) {
            ulonglong2 y2 = *reinterpret_cast<const ulonglong2*>(&YsT[k * YT_STR + t0]); // (t0,t0+1),(t2,t3)
            float4 w4 = *reinterpret_cast<const float4*>(&Wsh[k * W1_STR + j0]);
            u64 w0 = pack2(w4.x), w1 = pack2(w4.y), w2 = pack2(w4.z), w3 = pack2(w4.w);
            ffma2(acc1p[0], y2.x, w0); ffma2(acc1p[1], y2.y, w0);
            ffma2(acc1p[2], y2.x, w1); ffma2(acc1p[3], y2.y, w1);
            ffma2(acc1p[4], y2.x, w2); ffma2(acc1p[5], y2.y, w2);
            ffma2(acc1p[6], y2.x, w3); ffma2(acc1p[7], y2.y, w3);
        }

        // ---- bias + exact gelu -> HsTd (duplicated pairs) ----
#pragma unroll
        for (int jj = 0; jj < 4; jj++) {
            float bj = __ldg(&b1[c * HC + j0 + jj]);
#pragma unroll
            for (int tp = 0; tp < 2; tp++) {
                float2 h = unpack2(acc1p[jj * 2 + tp]);
                h.x += bj; h.y += bj;
                float gx = 0.5f * h.x * (1.0f + erff(h.x * 0.70710678118654752f));
                float gy = 0.5f * h.y * (1.0f + erff(h.y * 0.70710678118654752f));
                HsTd[(j0 + jj) * HD_STR + t0 + tp * 2 + 0] = make_float2(gx, gx);
                HsTd[(j0 + jj) * HD_STR + t0 + tp * 2 + 1] = make_float2(gy, gy);
            }
        }
        __syncthreads();   // W free (GEMM1 done), HsTd ready

        // ---- stage W2 chunk [64 j][128 a] (float4, coalesced) ----
        const float* W2c = W2 + (size_t)(c * HC) * AD;
#pragma unroll
        for (int i = 0; i < 8; i++) {
            int e  = tid + 256 * i;              // 2048 float4
            int j  = e >> 5;
            int a4 = (e & 31) << 2;
            float4 v = *reinterpret_cast<const float4*>(&W2c[(size_t)j * AD + a4]);
            *reinterpret_cast<float4*>(&Wsh[j * W2_STR + a4]) = v;
        }
        __syncthreads();

        // ---- GEMM2: acc2p += Hchunk @ W2chunk (all operands pre-packed f32x2) ----
#pragma unroll 4
        for (int j = 0; j < HC; j++) {
            ulonglong2 gA = *reinterpret_cast<const ulonglong2*>(&HsTd[j * HD_STR + t0]);     // (g0,g0),(g1,g1)
            ulonglong2 gB = *reinterpret_cast<const ulonglong2*>(&HsTd[j * HD_STR + t0 + 2]); // (g2,g2),(g3,g3)
            ulonglong2 wA = *reinterpret_cast<const ulonglong2*>(&Wsh[j * W2_STR + c0]);
            ulonglong2 wB = *reinterpret_cast<const ulonglong2*>(&Wsh[j * W2_STR + c0 + 64]);
            ffma2(acc2p[0],  gA.x, wA.x); ffma2(acc2p[1],  gA.x, wA.y);
            ffma2(acc2p[2],  gA.x, wB.x); ffma2(acc2p[3],  gA.x, wB.y);
            ffma2(acc2p[4],  gA.y, wA.x); ffma2(acc2p[5],  gA.y, wA.y);
            ffma2(acc2p[6],  gA.y, wB.x); ffma2(acc2p[7],  gA.y, wB.y);
            ffma2(acc2p[8],  gB.x, wA.x); ffma2(acc2p[9],  gB.x, wA.y);
            ffma2(acc2p[10], gB.x, wB.x); ffma2(acc2p[11], gB.x, wB.y);
            ffma2(acc2p[12], gB.y, wA.x); ffma2(acc2p[13], gB.y, wA.y);
            ffma2(acc2p[14], gB.y, wB.x); ffma2(acc2p[15], gB.y, wB.y);
        }
    }

    // ---- epilogue: out = x + acc2 + b2 (float4) ----
#pragma unroll
    for (int tt2 = 0; tt2 < 4; tt2++) {
        size_t row = (T0 + t0 + tt2) * (size_t)AD;
        float2 lo0 = unpack2(acc2p[tt2 * 4 + 0]);
        float2 lo1 = unpack2(acc2p[tt2 * 4 + 1]);
        float2 hi0 = unpack2(acc2p[tt2 * 4 + 2]);
        float2 hi1 = unpack2(acc2p[tt2 * 4 + 3]);
        {
            float4 xv = *reinterpret_cast<const float4*>(&g_x[row + c0]);
            float4 o;
            o.x = xv.x + lo0.x + __ldg(&b2[c0 + 0]);
            o.y = xv.y + lo0.y + __ldg(&b2[c0 + 1]);
            o.z = xv.z + lo1.x + __ldg(&b2[c0 + 2]);
            o.w = xv.w + lo1.y + __ldg(&b2[c0 + 3]);
            *reinterpret_cast<float4*>(&Out[row + c0]) = o;
        }
        {
            float4 xv = *reinterpret_cast<const float4*>(&g_x[row + c0 + 64]);
            float4 o;
            o.x = xv.x + hi0.x + __ldg(&b2[c0 + 64]);
            o.y = xv.y + hi0.y + __ldg(&b2[c0 + 65]);
            o.z = xv.z + hi1.x + __ldg(&b2[c0 + 66]);
            o.w = xv.w + hi1.y + __ldg(&b2[c0 + 67]);
            *reinterpret_cast<float4*>(&Out[row + c0 + 64]) = o;
        }
    }
}

// ===========================================================================
extern "C" void kernel_launch(void* const* d_in, const int* in_sizes, int n_in,
                              void* d_out, int out_size)
{
    const float* Q    = (const float*)d_in[0];
    const float* K    = (const float*)d_in[1];
    const float* V    = (const float*)d_in[2];
    const int*   mask = (const int*)  d_in[3];
    const float* ln1g = (const float*)d_in[4];
    const float* ln1b = (const float*)d_in[5];
    const float* ln2g = (const float*)d_in[6];
    const float* ln2b = (const float*)d_in[7];
    const float* W1   = (const float*)d_in[8];
    const float* b1   = (const float*)d_in[9];
    const float* W2   = (const float*)d_in[10];
    const float* b2   = (const float*)d_in[11];
    float* Out = (float*)d_out;

    static bool attr_set = false;
    if (!attr_set) {
        cudaFuncSetAttribute(bev_fused_kernel,
                             cudaFuncAttributeMaxDynamicSharedMemorySize,
                             SMEM_BYTES);
        attr_set = true;
    }

    bev_fused_kernel<<<NTOK / TT, 256, SMEM_BYTES>>>(
        Q, K, V, mask, ln1g, ln1b, ln2g, ln2b, W1, b1, W2, b2, Out);
}

// round 7
// speedup vs baseline: 2.2404x; 1.5487x over previous
#include <cuda_runtime.h>
#include <math.h>
#include <stdint.h>

#define NRTOK 16384
#define NTOK  32768      // B*Nr
#define MM    64
#define AD    128
#define HIDN  512
#define TT    64         // tokens per CTA tile
#define HC    64         // hidden chunk
#define SCALE 0.17677669529663687f  // 1/sqrt(32)

#define YS_STR 132       // Ys  [tok][k]  stride (words): 132 % 32 == 4 -> A-frag conflict-free
#define W1_STR 72        // W1s [k][j]    stride: 72  % 32 == 8 -> B-frag conflict-free
#define W2_STR 136       // W2s [j][a]    stride: 136 % 32 == 8 -> B-frag conflict-free
#define HS_STR 68        // Hs  [tok][j]  stride: 68  % 32 == 4 -> A-frag conflict-free

// smem map (bytes):
//   [0, 33792)        Ys : u32[64*132]   tf32 y tile [tok][k] (persists through MLP)
//   [33792, 70656)    Ws : u32           W1 chunk [128][64] s72  OR  W2 chunk [64][128] s136
//   [70656, 88064)    union: Hs u32[64*68] tf32 gelu(h) [tok][j] | attention scratch
#define SM_W_OFF 33792
#define SM_U_OFF 70656
#define SMEM_BYTES 88064

__device__ __forceinline__ uint32_t cvt_tf32(float x) {
    uint32_t r; asm("cvt.rna.tf32.f32 %0, %1;" : "=r"(r) : "f"(x)); return r;
}
__device__ __forceinline__ void mma_tf32(float* d, uint32_t a0, uint32_t a1,
                                         uint32_t a2, uint32_t a3,
                                         uint32_t b0, uint32_t b1) {
    asm("mma.sync.aligned.m16n8k8.row.col.f32.tf32.tf32.f32 "
        "{%0,%1,%2,%3}, {%4,%5,%6,%7}, {%8,%9}, {%0,%1,%2,%3};"
        : "+f"(d[0]), "+f"(d[1]), "+f"(d[2]), "+f"(d[3])
        : "r"(a0), "r"(a1), "r"(a2), "r"(a3), "r"(b0), "r"(b1));
}

// scratch: x = post-LN1 (residual base for final add)
__device__ float g_x[NTOK * AD];

__global__ __launch_bounds__(256, 2)
void bev_fused_kernel(const float* __restrict__ Q, const float* __restrict__ K,
                      const float* __restrict__ V, const int* __restrict__ mask,
                      const float* __restrict__ ln1g, const float* __restrict__ ln1b,
                      const float* __restrict__ ln2g, const float* __restrict__ ln2b,
                      const float* __restrict__ W1, const float* __restrict__ b1,
                      const float* __restrict__ W2, const float* __restrict__ b2,
                      float* __restrict__ Out)
{
    extern __shared__ char smem_raw[];
    uint32_t* Ys = reinterpret_cast<uint32_t*>(smem_raw);
    uint32_t* Ws = reinterpret_cast<uint32_t*>(smem_raw + SM_W_OFF);
    uint32_t* Hs = reinterpret_cast<uint32_t*>(smem_raw + SM_U_OFF);
    // attention scratch views (union with Hs)
    float*  Ls  = reinterpret_cast<float*>(smem_raw + SM_U_OFF);           // 256
    float*  As  = Ls + 256;                                                // 256
    float*  Ps  = As + 256;                                                // 256
    float*  Ms  = Ps + 256;                                                // 64
    float2* Rs  = reinterpret_cast<float2*>(Ms + MM);                      // 4
    float2* Rs2 = Rs + 4;                                                  // 4

    const int tid  = threadIdx.x;
    const int lane = tid & 31;
    const int wid  = tid >> 5;
    const size_t T0 = (size_t)blockIdx.x * TT;

    // attention roles: warp w -> head h=w&3, m-base mb=(w>>2)*32, lane = d
    const int hh = wid & 3;
    const int mb = (wid >> 2) << 5;
    const int a  = (hh << 5) + lane;

    // per-thread LN params (a == tid for tid<128)
    float l1gv = 0.f, l1bv = 0.f, l2gv = 0.f, l2bv = 0.f;
    if (tid < AD) {
        l1gv = ln1g[tid]; l1bv = ln1b[tid];
        l2gv = ln2g[tid]; l2bv = ln2b[tid];
    }

    // =========================== phase 1: attention + LN1 + LN2 ===========================
    for (int tl = 0; tl < TT; tl++) {
        const size_t t = T0 + tl;

        if (tid < MM)
            Ms[tid] = mask[((t & (NRTOK - 1)) << 6) + tid] ? -1e30f : 0.0f;

        const float q = Q[t * AD + a];

        // logits: p[i] = q_d * K[mb+i][a], coalesced 128B warp loads
        const float* Kp = K + (t * MM + mb) * AD + a;
        float p[32];
#pragma unroll
        for (int i = 0; i < 32; i++) p[i] = q * Kp[(size_t)i * AD];

        // butterfly transpose-reduce: lane l ends with full d-sum for m = mb + l
#pragma unroll
        for (int s = 16; s >= 1; s >>= 1) {
            const bool hi = (lane & s) != 0;
#pragma unroll
            for (int i = 0; i < 16; i++) {
                if (i < s) {
                    float send = hi ? p[i] : p[i + s];
                    float recv = __shfl_xor_sync(0xffffffffu, send, s);
                    p[i] = (hi ? p[i + s] : p[i]) + recv;
                }
            }
        }
        __syncthreads();                                   // S1
        Ls[(hh << 6) + mb + lane] = p[0] * SCALE + Ms[mb + lane];
        __syncthreads();                                   // S2

        // softmax: warp w<4 handles head w over 64 m
        if (wid < 4) {
            float l0 = Ls[(wid << 6) + lane];
            float l1 = Ls[(wid << 6) + 32 + lane];
            float mx = fmaxf(l0, l1);
#pragma unroll
            for (int s = 16; s >= 1; s >>= 1)
                mx = fmaxf(mx, __shfl_xor_sync(0xffffffffu, mx, s));
            float e0 = __expf(l0 - mx), e1 = __expf(l1 - mx);
            float ss = e0 + e1;
#pragma unroll
            for (int s = 16; s >= 1; s >>= 1)
                ss += __shfl_xor_sync(0xffffffffu, ss, s);
            float inv = 1.0f / ss;
            As[(wid << 6) + lane]      = e0 * inv;
            As[(wid << 6) + 32 + lane] = e1 * inv;
        }
        __syncthreads();                                   // S3

        // out[a] = sum_m attn[h][m] * V[m][a], coalesced V stream
        {
            const int aV = tid & 127;
            const int gV = tid >> 7;
            const int hA = aV >> 5;
            const float* Vp = V + (t * MM + ((size_t)gV << 5)) * AD + aV;
            float acc = 0.0f;
#pragma unroll
            for (int i = 0; i < 32; i++)
                acc += As[(hA << 6) + (gV << 5) + i] * Vp[(size_t)i * AD];
            Ps[tid] = acc;
        }
        __syncthreads();                                   // S4

        float x = 0.0f, xn = 0.0f;
        if (tid < AD) {
            x = q + Ps[tid] + Ps[tid + 128];
            float sx = x, sxx = x * x;
#pragma unroll
            for (int s = 16; s >= 1; s >>= 1) {
                sx  += __shfl_xor_sync(0xffffffffu, sx,  s);
                sxx += __shfl_xor_sync(0xffffffffu, sxx, s);
            }
            if (lane == 0) Rs[wid] = make_float2(sx, sxx);
        }
        __syncthreads();                                   // S5
        if (tid < AD) {
            float tsum = Rs[0].x + Rs[1].x + Rs[2].x + Rs[3].x;
            float tsq  = Rs[0].y + Rs[1].y + Rs[2].y + Rs[3].y;
            float mu   = tsum * (1.0f / AD);
            float var  = tsq * (1.0f / AD) - mu * mu;
            float rstd = rsqrtf(var + 1e-5f);
            xn = (x - mu) * rstd * l1gv + l1bv;
            float sx = xn, sxx = xn * xn;
#pragma unroll
            for (int s = 16; s >= 1; s >>= 1) {
                sx  += __shfl_xor_sync(0xffffffffu, sx,  s);
                sxx += __shfl_xor_sync(0xffffffffu, sxx, s);
            }
            if (lane == 0) Rs2[wid] = make_float2(sx, sxx);
        }
        __syncthreads();                                   // S6
        if (tid < AD) {
            float tsum = Rs2[0].x + Rs2[1].x + Rs2[2].x + Rs2[3].x;
            float tsq  = Rs2[0].y + Rs2[1].y + Rs2[2].y + Rs2[3].y;
            float mu2   = tsum * (1.0f / AD);
            float var2  = tsq * (1.0f / AD) - mu2 * mu2;
            float rstd2 = rsqrtf(var2 + 1e-5f);
            float y = (xn - mu2) * rstd2 * l2gv + l2bv;
            g_x[t * AD + tid] = xn;
            Ys[tl * YS_STR + tid] = cvt_tf32(y);           // y tile, tf32, [tok][k]
        }
    }

    // =========================== phase 2: MLP via tf32 tensor cores ===========================
    // warp w: M-tile tm = w&3 (tokens tbase..tbase+15), N-half nh = w>>2
    const int tm    = wid & 3;
    const int nh    = wid >> 2;
    const int tbase = tm << 4;
    const int gid   = lane >> 2;     // 0..7
    const int tig   = lane & 3;      // 0..3

    float acc2[8][4];                // GEMM2 accum: 8 n8-tiles over cols nh*64..+63
#pragma unroll
    for (int i = 0; i < 8; i++)
#pragma unroll
        for (int k = 0; k < 4; k++) acc2[i][k] = 0.0f;

    for (int c = 0; c < HIDN / HC; c++) {
        __syncthreads();   // W/Hs free; also attn->MLP transition on first iter

        // ---- stage W1 chunk [128 k][64 j] -> tf32, stride 72 ----
        const float* W1c = W1 + c * HC;
#pragma unroll
        for (int i = 0; i < 8; i++) {
            int e  = tid + 256 * i;              // 2048 float4
            int k  = e >> 4;
            int j4 = (e & 15) << 2;
            float4 v = *reinterpret_cast<const float4*>(&W1c[(size_t)k * HIDN + j4]);
            uint4 tv = make_uint4(cvt_tf32(v.x), cvt_tf32(v.y), cvt_tf32(v.z), cvt_tf32(v.w));
            *reinterpret_cast<uint4*>(&Ws[k * W1_STR + j4]) = tv;
        }
        __syncthreads();

        // ---- GEMM1: H[64 tok][64 hid] = Ys @ W1chunk (16 k8-steps) ----
        float acc1[4][4];
#pragma unroll
        for (int i = 0; i < 4; i++)
#pragma unroll
            for (int k = 0; k < 4; k++) acc1[i][k] = 0.0f;

#pragma unroll 4
        for (int kk = 0; kk < 16; kk++) {
            const int k0 = kk << 3;
            uint32_t a0 = Ys[(tbase + gid)     * YS_STR + k0 + tig];
            uint32_t a1 = Ys[(tbase + gid + 8) * YS_STR + k0 + tig];
            uint32_t a2 = Ys[(tbase + gid)     * YS_STR + k0 + tig + 4];
            uint32_t a3 = Ys[(tbase + gid + 8) * YS_STR + k0 + tig + 4];
#pragma unroll
            for (int nt = 0; nt < 4; nt++) {
                const int jc = (nh << 5) + (nt << 3) + gid;
                uint32_t b0 = Ws[(k0 + tig)     * W1_STR + jc];
                uint32_t b1 = Ws[(k0 + tig + 4) * W1_STR + jc];
                mma_tf32(acc1[nt], a0, a1, a2, a3, b0, b1);
            }
        }

        // ---- bias + exact gelu -> Hs (tf32 pairs) ----
#pragma unroll
        for (int nt = 0; nt < 4; nt++) {
            const int j = (nh << 5) + (nt << 3) + (tig << 1);
            float bja = __ldg(&b1[c * HC + j]);
            float bjb = __ldg(&b1[c * HC + j + 1]);
            float h00 = acc1[nt][0] + bja, h01 = acc1[nt][1] + bjb;
            float h10 = acc1[nt][2] + bja, h11 = acc1[nt][3] + bjb;
            float g00 = 0.5f * h00 * (1.0f + erff(h00 * 0.70710678118654752f));
            float g01 = 0.5f * h01 * (1.0f + erff(h01 * 0.70710678118654752f));
            float g10 = 0.5f * h10 * (1.0f + erff(h10 * 0.70710678118654752f));
            float g11 = 0.5f * h11 * (1.0f + erff(h11 * 0.70710678118654752f));
            *reinterpret_cast<uint2*>(&Hs[(tbase + gid)     * HS_STR + j]) =
                make_uint2(cvt_tf32(g00), cvt_tf32(g01));
            *reinterpret_cast<uint2*>(&Hs[(tbase + gid + 8) * HS_STR + j]) =
                make_uint2(cvt_tf32(g10), cvt_tf32(g11));
        }
        __syncthreads();   // W free (GEMM1 done), Hs ready

        // ---- stage W2 chunk [64 j][128 a] -> tf32, stride 136 ----
        const float* W2c = W2 + (size_t)(c * HC) * AD;
#pragma unroll
        for (int i = 0; i < 8; i++) {
            int e  = tid + 256 * i;              // 2048 float4
            int j  = e >> 5;
            int a4 = (e & 31) << 2;
            float4 v = *reinterpret_cast<const float4*>(&W2c[(size_t)j * AD + a4]);
            uint4 tv = make_uint4(cvt_tf32(v.x), cvt_tf32(v.y), cvt_tf32(v.z), cvt_tf32(v.w));
            *reinterpret_cast<uint4*>(&Ws[j * W2_STR + a4]) = tv;
        }
        __syncthreads();

        // ---- GEMM2: acc2 += Hchunk @ W2chunk (8 k8-steps) ----
#pragma unroll 4
        for (int kk = 0; kk < 8; kk++) {
            const int j0 = kk << 3;
            uint32_t a0 = Hs[(tbase + gid)     * HS_STR + j0 + tig];
            uint32_t a1 = Hs[(tbase + gid + 8) * HS_STR + j0 + tig];
            uint32_t a2 = Hs[(tbase + gid)     * HS_STR + j0 + tig + 4];
            uint32_t a3 = Hs[(tbase + gid + 8) * HS_STR + j0 + tig + 4];
#pragma unroll
            for (int nt = 0; nt < 8; nt++) {
                const int ac = (nh << 6) + (nt << 3) + gid;
                uint32_t b0 = Ws[(j0 + tig)     * W2_STR + ac];
                uint32_t b1 = Ws[(j0 + tig + 4) * W2_STR + ac];
                mma_tf32(acc2[nt], a0, a1, a2, a3, b0, b1);
            }
        }
    }

    // ---- epilogue: out = x + acc2 + b2 (float2 per d-pair) ----
#pragma unroll
    for (int nt = 0; nt < 8; nt++) {
        const int av = (nh << 6) + (nt << 3) + (tig << 1);
        float b2a = __ldg(&b2[av]);
        float b2b = __ldg(&b2[av + 1]);
        size_t r0 = (T0 + tbase + gid) * (size_t)AD + av;
        size_t r1 = (T0 + tbase + gid + 8) * (size_t)AD + av;
        float2 x0 = *reinterpret_cast<const float2*>(&g_x[r0]);
        float2 x1 = *reinterpret_cast<const float2*>(&g_x[r1]);
        float2 o0 = make_float2(x0.x + acc2[nt][0] + b2a, x0.y + acc2[nt][1] + b2b);
        float2 o1 = make_float2(x1.x + acc2[nt][2] + b2a, x1.y + acc2[nt][3] + b2b);
        *reinterpret_cast<float2*>(&Out[r0]) = o0;
        *reinterpret_cast<float2*>(&Out[r1]) = o1;
    }
}

// ===========================================================================
extern "C" void kernel_launch(void* const* d_in, const int* in_sizes, int n_in,
                              void* d_out, int out_size)
{
    const float* Q    = (const float*)d_in[0];
    const float* K    = (const float*)d_in[1];
    const float* V    = (const float*)d_in[2];
    const int*   mask = (const int*)  d_in[3];
    const float* ln1g = (const float*)d_in[4];
    const float* ln1b = (const float*)d_in[5];
    const float* ln2g = (const float*)d_in[6];
    const float* ln2b = (const float*)d_in[7];
    const float* W1   = (const float*)d_in[8];
    const float* b1   = (const float*)d_in[9];
    const float* W2   = (const float*)d_in[10];
    const float* b2   = (const float*)d_in[11];
    float* Out = (float*)d_out;

    static bool attr_set = false;
    if (!attr_set) {
        cudaFuncSetAttribute(bev_fused_kernel,
                             cudaFuncAttributeMaxDynamicSharedMemorySize,
                             SMEM_BYTES);
        attr_set = true;
    }

    bev_fused_kernel<<<NTOK / TT, 256, SMEM_BYTES>>>(
        Q, K, V, mask, ln1g, ln1b, ln2g, ln2b, W1, b1, W2, b2, Out);
}